// round 1
// baseline (speedup 1.0000x reference)
#include <cuda_runtime.h>
#include <cstdint>

// Problem constants
#define B_SZ   8
#define T_SZ   4096
#define C_SZ   1024
#define M_TOT  (B_SZ * T_SZ)       // 32768
#define H_SZ   16
#define D_SZ   64

// Scratch (static device globals — no runtime allocation)
__device__ float g_q[(size_t)M_TOT * C_SZ];
__device__ float g_k[(size_t)M_TOT * C_SZ];
__device__ float g_v[(size_t)M_TOT * C_SZ];
__device__ float g_y[(size_t)M_TOT * C_SZ];

// ---------------------------------------------------------------------------
// tf32 mma.sync GEMM:  C[M,N] = A[M,K] @ W[N,K]^T + bias[N]
// BM=128, BN=128, BK=16, 256 threads (8 warps: 4 along M x 2 along N)
// Each warp: 32x64 tile = 2x8 m16n8k8 mma tiles.
// ---------------------------------------------------------------------------
#define BM 128
#define BN 128
#define BK 16
#define BKP 20   // padded row length (conflict-free fragment loads, 16B aligned)

__device__ __forceinline__ float f2tf32(float x) {
    uint32_t u;
    asm("cvt.rna.tf32.f32 %0, %1;" : "=r"(u) : "f"(x));
    return __uint_as_float(u);
}

__device__ __forceinline__ void mma8(float* c, const uint32_t* a, uint32_t b0, uint32_t b1) {
    asm volatile(
        "mma.sync.aligned.m16n8k8.row.col.f32.tf32.tf32.f32 "
        "{%0,%1,%2,%3},{%4,%5,%6,%7},{%8,%9},{%0,%1,%2,%3};\n"
        : "+f"(c[0]), "+f"(c[1]), "+f"(c[2]), "+f"(c[3])
        : "r"(a[0]), "r"(a[1]), "r"(a[2]), "r"(a[3]), "r"(b0), "r"(b1));
}

__global__ __launch_bounds__(256, 2)
void gemm_tf32(const float* __restrict__ A, const float* __restrict__ W,
               const float* __restrict__ bias, float* __restrict__ C,
               int M, int N, int K)
{
    __shared__ float As[2][BM][BKP];
    __shared__ float Bs[2][BN][BKP];

    const int tid  = threadIdx.x;
    const int lane = tid & 31;
    const int wid  = tid >> 5;
    const int warp_m = wid & 3;   // 0..3  -> 32 rows each
    const int warp_n = wid >> 2;  // 0..1  -> 64 cols each
    const int g  = lane >> 2;     // groupID 0..7
    const int tc = lane & 3;      // threadID_in_group 0..3

    const long bM = (long)blockIdx.y * BM;
    const long bN = (long)blockIdx.x * BN;

    const float* Aptr = A + bM * K;
    const float* Wptr = W + bN * K;

    // gmem load mapping: 128x16 floats = 512 float4; 256 thr * 2 float4
    const int ldr0 = tid >> 2;        // row 0..63 (i adds 64)
    const int ldc  = (tid & 3) * 4;   // col 0,4,8,12

    float acc[2][8][4] = {};
    float4 ra[2], rb[2];

    // prologue: load tile 0
    {
        const int k0 = 0;
        #pragma unroll
        for (int i = 0; i < 2; i++) {
            int row = ldr0 + i * 64;
            ra[i] = *(const float4*)(Aptr + (long)row * K + k0 + ldc);
            rb[i] = *(const float4*)(Wptr + (long)row * K + k0 + ldc);
        }
        #pragma unroll
        for (int i = 0; i < 2; i++) {
            int row = ldr0 + i * 64;
            float* as = &As[0][row][ldc];
            as[0] = f2tf32(ra[i].x); as[1] = f2tf32(ra[i].y);
            as[2] = f2tf32(ra[i].z); as[3] = f2tf32(ra[i].w);
            float* bs = &Bs[0][row][ldc];
            bs[0] = f2tf32(rb[i].x); bs[1] = f2tf32(rb[i].y);
            bs[2] = f2tf32(rb[i].z); bs[3] = f2tf32(rb[i].w);
        }
    }
    __syncthreads();

    const int NT = K / BK;   // 64
    for (int t = 0; t < NT; t++) {
        const int cur = t & 1;

        // issue next-tile gmem loads early
        if (t + 1 < NT) {
            const int k0 = (t + 1) * BK;
            #pragma unroll
            for (int i = 0; i < 2; i++) {
                int row = ldr0 + i * 64;
                ra[i] = *(const float4*)(Aptr + (long)row * K + k0 + ldc);
                rb[i] = *(const float4*)(Wptr + (long)row * K + k0 + ldc);
            }
        }

        // compute on current buffer
        #pragma unroll
        for (int kk = 0; kk < BK / 8; kk++) {
            const int kb = kk * 8;
            uint32_t af[2][4];
            #pragma unroll
            for (int mi = 0; mi < 2; mi++) {
                int r0 = warp_m * 32 + mi * 16 + g;
                af[mi][0] = __float_as_uint(As[cur][r0    ][kb + tc    ]);
                af[mi][1] = __float_as_uint(As[cur][r0 + 8][kb + tc    ]);
                af[mi][2] = __float_as_uint(As[cur][r0    ][kb + tc + 4]);
                af[mi][3] = __float_as_uint(As[cur][r0 + 8][kb + tc + 4]);
            }
            #pragma unroll
            for (int ni = 0; ni < 8; ni++) {
                int c0 = warp_n * 64 + ni * 8 + g;
                uint32_t b0 = __float_as_uint(Bs[cur][c0][kb + tc    ]);
                uint32_t b1 = __float_as_uint(Bs[cur][c0][kb + tc + 4]);
                #pragma unroll
                for (int mi = 0; mi < 2; mi++)
                    mma8(acc[mi][ni], af[mi], b0, b1);
            }
        }

        if (t + 1 < NT) {
            __syncthreads();
            const int nxt = 1 - cur;
            #pragma unroll
            for (int i = 0; i < 2; i++) {
                int row = ldr0 + i * 64;
                float* as = &As[nxt][row][ldc];
                as[0] = f2tf32(ra[i].x); as[1] = f2tf32(ra[i].y);
                as[2] = f2tf32(ra[i].z); as[3] = f2tf32(ra[i].w);
                float* bs = &Bs[nxt][row][ldc];
                bs[0] = f2tf32(rb[i].x); bs[1] = f2tf32(rb[i].y);
                bs[2] = f2tf32(rb[i].z); bs[3] = f2tf32(rb[i].w);
            }
            __syncthreads();
        }
    }

    // epilogue: add bias, store
    #pragma unroll
    for (int mi = 0; mi < 2; mi++) {
        long r0 = bM + warp_m * 32 + mi * 16 + g;
        #pragma unroll
        for (int ni = 0; ni < 8; ni++) {
            long c = bN + warp_n * 64 + ni * 8 + tc * 2;
            float bb0 = bias[c], bb1 = bias[c + 1];
            float2 o0 = make_float2(acc[mi][ni][0] + bb0, acc[mi][ni][1] + bb1);
            float2 o1 = make_float2(acc[mi][ni][2] + bb0, acc[mi][ni][3] + bb1);
            *(float2*)(C + r0 * N + c)       = o0;
            *(float2*)(C + (r0 + 8) * N + c) = o1;
        }
    }
}

// ---------------------------------------------------------------------------
// Banded window-3 attention: one warp per token, loops over 16 heads.
// q,k,v,y layout: [B*T, C] rows, head h occupies cols [h*64, h*64+64).
// ---------------------------------------------------------------------------
__global__ __launch_bounds__(128)
void attn_band3(const float* __restrict__ q, const float* __restrict__ k,
                const float* __restrict__ vv, float* __restrict__ y)
{
    const int lane = threadIdx.x & 31;
    const int warp = threadIdx.x >> 5;
    const long r = (long)blockIdx.x * 4 + warp;     // token row 0..32767
    const int  t = (int)(r & (T_SZ - 1));           // position within batch
    const bool ok1 = (t >= 1), ok2 = (t >= 2);
    const float scale = 0.125f;                     // 1/sqrt(64)
    const long rowb = r * C_SZ;

    #pragma unroll 1
    for (int h = 0; h < H_SZ; h++) {
        const long base = rowb + h * D_SZ;
        float q0 = q[base + lane], q1 = q[base + 32 + lane];

        float s0 = q0 * k[base + lane] + q1 * k[base + 32 + lane];
        float s1 = 0.f, s2 = 0.f;
        if (ok1) { long b1 = base - C_SZ;     s1 = q0 * k[b1 + lane] + q1 * k[b1 + 32 + lane]; }
        if (ok2) { long b2 = base - 2 * C_SZ; s2 = q0 * k[b2 + lane] + q1 * k[b2 + 32 + lane]; }

        #pragma unroll
        for (int off = 16; off; off >>= 1) {
            s0 += __shfl_xor_sync(0xffffffffu, s0, off);
            s1 += __shfl_xor_sync(0xffffffffu, s1, off);
            s2 += __shfl_xor_sync(0xffffffffu, s2, off);
        }
        s0 *= scale; s1 *= scale; s2 *= scale;

        float m = s0;
        if (ok1 && s1 > m) m = s1;
        if (ok2 && s2 > m) m = s2;
        float p0 = __expf(s0 - m);
        float p1 = ok1 ? __expf(s1 - m) : 0.f;
        float p2 = ok2 ? __expf(s2 - m) : 0.f;
        float inv = 1.f / (p0 + p1 + p2);
        p0 *= inv; p1 *= inv; p2 *= inv;

        float y0 = p0 * vv[base + lane];
        float y1 = p0 * vv[base + 32 + lane];
        if (ok1) { long b1 = base - C_SZ;     y0 += p1 * vv[b1 + lane]; y1 += p1 * vv[b1 + 32 + lane]; }
        if (ok2) { long b2 = base - 2 * C_SZ; y0 += p2 * vv[b2 + lane]; y1 += p2 * vv[b2 + 32 + lane]; }

        y[base + lane]      = y0;
        y[base + 32 + lane] = y1;
    }
}

// ---------------------------------------------------------------------------
extern "C" void kernel_launch(void* const* d_in, const int* in_sizes, int n_in,
                              void* d_out, int out_size)
{
    const float* x  = (const float*)d_in[0];
    const float* Wq = (const float*)d_in[1];
    const float* bq = (const float*)d_in[2];
    const float* Wk = (const float*)d_in[3];
    const float* bk = (const float*)d_in[4];
    const float* Wv = (const float*)d_in[5];
    const float* bv = (const float*)d_in[6];
    const float* Wo = (const float*)d_in[7];
    const float* bo = (const float*)d_in[8];
    float* out = (float*)d_out;

    void *pq, *pk, *pv, *py;
    cudaGetSymbolAddress(&pq, g_q);
    cudaGetSymbolAddress(&pk, g_k);
    cudaGetSymbolAddress(&pv, g_v);
    cudaGetSymbolAddress(&py, g_y);

    dim3 grid(C_SZ / BN, M_TOT / BM);   // (8, 256)
    gemm_tf32<<<grid, 256>>>(x, Wq, bq, (float*)pq, M_TOT, C_SZ, C_SZ);
    gemm_tf32<<<grid, 256>>>(x, Wk, bk, (float*)pk, M_TOT, C_SZ, C_SZ);
    gemm_tf32<<<grid, 256>>>(x, Wv, bv, (float*)pv, M_TOT, C_SZ, C_SZ);

    attn_band3<<<M_TOT / 4, 128>>>((const float*)pq, (const float*)pk,
                                   (const float*)pv, (float*)py);

    gemm_tf32<<<grid, 256>>>((const float*)py, Wo, bo, out, M_TOT, C_SZ, C_SZ);
}

// round 12
// speedup vs baseline: 1.2689x; 1.2689x over previous
#include <cuda_runtime.h>
#include <cstdint>

// Problem constants
#define B_SZ   8
#define T_SZ   4096
#define C_SZ   1024
#define M_TOT  (B_SZ * T_SZ)       // 32768
#define H_SZ   16
#define D_SZ   64

// ---------------- scratch (static device globals, no runtime alloc) --------
__device__ float g_xc[(size_t)M_TOT * C_SZ];          // tf32-rounded x
__device__ float g_wc[4][(size_t)C_SZ * C_SZ];        // tf32-rounded weights
__device__ float g_q[(size_t)M_TOT * C_SZ];
__device__ float g_k[(size_t)M_TOT * C_SZ];
__device__ float g_v[(size_t)M_TOT * C_SZ];
__device__ float g_y[(size_t)M_TOT * C_SZ];           // tf32-rounded attn out

// ---------------- helpers ---------------------------------------------------
__device__ __forceinline__ uint32_t smem_u32(const void* p) {
    uint32_t a;
    asm("{ .reg .u64 t; cvta.to.shared.u64 t, %1; cvt.u32.u64 %0, t; }"
        : "=r"(a) : "l"(p));
    return a;
}
__device__ __forceinline__ float f2tf32(float x) {
    uint32_t u;
    asm("cvt.rna.tf32.f32 %0, %1;" : "=r"(u) : "f"(x));
    return __uint_as_float(u);
}
__device__ __forceinline__ void cp16(uint32_t dst, const void* src) {
    asm volatile("cp.async.cg.shared.global [%0], [%1], 16;"
                 :: "r"(dst), "l"(src) : "memory");
}
#define CP_COMMIT() asm volatile("cp.async.commit_group;" ::: "memory")
#define CP_WAIT(n)  asm volatile("cp.async.wait_group %0;" :: "n"(n) : "memory")

__device__ __forceinline__ void ldsm4(uint32_t* r, uint32_t addr) {
    asm volatile("ldmatrix.sync.aligned.m8n8.x4.shared.b16 {%0,%1,%2,%3}, [%4];"
                 : "=r"(r[0]), "=r"(r[1]), "=r"(r[2]), "=r"(r[3]) : "r"(addr));
}
__device__ __forceinline__ void mma8(float* c, const uint32_t* a,
                                     uint32_t b0, uint32_t b1) {
    asm volatile(
        "mma.sync.aligned.m16n8k8.row.col.f32.tf32.tf32.f32 "
        "{%0,%1,%2,%3},{%4,%5,%6,%7},{%8,%9},{%0,%1,%2,%3};\n"
        : "+f"(c[0]), "+f"(c[1]), "+f"(c[2]), "+f"(c[3])
        : "r"(a[0]), "r"(a[1]), "r"(a[2]), "r"(a[3]), "r"(b0), "r"(b1));
}

// ---------------- GEMM: C[M,1024] = A[M,1024] @ W[1024,1024]^T + bias ------
// mma.sync tf32, BM=128 BN=256 BK=32, 512 threads (16 warps, 4x4),
// 3-stage cp.async pipeline, ldmatrix.x4 fragment loads. Inputs pre-rounded.
#define BM 128
#define BN 256
#define BK 32
#define SA 36                         // padded floats per smem row
#define A_ST (BM * SA)                // 4608 floats
#define B_ST (BN * SA)                // 9216 floats
#define STG_FL (A_ST + B_ST)          // 13824 floats = 55296 B
#define STAGES 3
#define NCH (C_SZ / BK)               // 32
#define SM_TOTAL (STAGES * STG_FL * 4)  // 165888 B

__global__ __launch_bounds__(512, 1)
void gemm_tc(const float* __restrict__ A, const float* __restrict__ W,
             const float* __restrict__ bias, float* __restrict__ C)
{
    extern __shared__ __align__(128) float smem[];
    const uint32_t sbase = smem_u32(smem);

    const int tid  = threadIdx.x;
    const int lane = tid & 31;
    const int wid  = tid >> 5;
    const int wm   = wid & 3;     // 0..3 -> 32 rows
    const int wn   = wid >> 2;    // 0..3 -> 64 cols
    const int g    = lane >> 2;
    const int tc   = lane & 3;

    const long bM = (long)blockIdx.y * BM;
    const long bN = (long)blockIdx.x * BN;
    const float* Ab = A + bM * C_SZ;
    const float* Wb = W + bN * C_SZ;

    // gmem->smem loader for one BK chunk into stage s
    auto load_chunk = [&](int t, int s) {
        const int k0 = t * BK;
        const uint32_t as = sbase + (uint32_t)(s * STG_FL) * 4;
        const uint32_t bs = as + A_ST * 4;
        #pragma unroll
        for (int i = 0; i < 2; i++) {                 // A: 1024 x 16B
            int idx = tid + i * 512;
            int row = idx >> 3, c = idx & 7;
            cp16(as + (uint32_t)(row * SA + c * 4) * 4,
                 Ab + (long)row * C_SZ + k0 + c * 4);
        }
        #pragma unroll
        for (int i = 0; i < 4; i++) {                 // B: 2048 x 16B
            int idx = tid + i * 512;
            int row = idx >> 3, c = idx & 7;
            cp16(bs + (uint32_t)(row * SA + c * 4) * 4,
                 Wb + (long)row * C_SZ + k0 + c * 4);
        }
    };

    // per-thread ldmatrix base offsets (bytes within a stage)
    const uint32_t aoff =
        (uint32_t)((wm * 32 + ((lane >> 3) & 1) * 8 + (lane & 7)) * SA
                   + (lane >> 4) * 4) * 4;
    const uint32_t boff = (uint32_t)A_ST * 4 +
        (uint32_t)((wn * 64 + (lane >> 4) * 8 + (lane & 7)) * SA
                   + ((lane >> 3) & 1) * 4) * 4;

    float acc[2][8][4] = {};

    load_chunk(0, 0); CP_COMMIT();
    load_chunk(1, 1); CP_COMMIT();

    for (int t = 0; t < NCH; t++) {
        if (t + 2 < NCH) load_chunk(t + 2, (t + 2) % STAGES);
        CP_COMMIT();
        CP_WAIT(2);
        __syncthreads();

        const uint32_t stg = sbase + (uint32_t)((t % STAGES) * STG_FL) * 4;
        #pragma unroll
        for (int kk = 0; kk < BK / 8; kk++) {
            const uint32_t kb = kk * 32;   // 8 floats = 32 bytes
            uint32_t a[2][4];
            ldsm4(a[0], stg + aoff + kb);
            ldsm4(a[1], stg + aoff + 16 * SA * 4 + kb);
            #pragma unroll
            for (int p = 0; p < 4; p++) {
                uint32_t b[4];
                ldsm4(b, stg + boff + (uint32_t)(p * 16 * SA) * 4 + kb);
                mma8(acc[0][2 * p],     a[0], b[0], b[1]);
                mma8(acc[1][2 * p],     a[1], b[0], b[1]);
                mma8(acc[0][2 * p + 1], a[0], b[2], b[3]);
                mma8(acc[1][2 * p + 1], a[1], b[2], b[3]);
            }
        }
        __syncthreads();
    }

    // epilogue: bias add + store
    #pragma unroll
    for (int mi = 0; mi < 2; mi++) {
        long r0 = bM + wm * 32 + mi * 16 + g;
        #pragma unroll
        for (int ni = 0; ni < 8; ni++) {
            long c = bN + wn * 64 + ni * 8 + tc * 2;
            float bb0 = bias[c], bb1 = bias[c + 1];
            float2 o0 = make_float2(acc[mi][ni][0] + bb0, acc[mi][ni][1] + bb1);
            float2 o1 = make_float2(acc[mi][ni][2] + bb0, acc[mi][ni][3] + bb1);
            *(float2*)(C + r0 * C_SZ + c)       = o0;
            *(float2*)(C + (r0 + 8) * C_SZ + c) = o1;
        }
    }
}

// ---------------- fp32 -> tf32(rna) elementwise ----------------------------
__global__ void conv_tf32(const float* __restrict__ in, float* __restrict__ out,
                          long n4)
{
    long i = (long)blockIdx.x * blockDim.x + threadIdx.x;
    long stride = (long)gridDim.x * blockDim.x;
    for (; i < n4; i += stride) {
        float4 v = ((const float4*)in)[i];
        v.x = f2tf32(v.x); v.y = f2tf32(v.y);
        v.z = f2tf32(v.z); v.w = f2tf32(v.w);
        ((float4*)out)[i] = v;
    }
}

// ---------------- banded window-3 attention (y tf32-rounded) ---------------
__global__ __launch_bounds__(128)
void attn_band3(const float* __restrict__ q, const float* __restrict__ k,
                const float* __restrict__ vv, float* __restrict__ y)
{
    const int lane = threadIdx.x & 31;
    const int warp = threadIdx.x >> 5;
    const long r = (long)blockIdx.x * 4 + warp;
    const int  t = (int)(r & (T_SZ - 1));
    const bool ok1 = (t >= 1), ok2 = (t >= 2);
    const float scale = 0.125f;
    const long rowb = r * C_SZ;

    #pragma unroll 2
    for (int h = 0; h < H_SZ; h++) {
        const long base = rowb + h * D_SZ;
        float q0 = q[base + lane], q1 = q[base + 32 + lane];

        float s0 = q0 * k[base + lane] + q1 * k[base + 32 + lane];
        float s1 = 0.f, s2 = 0.f;
        if (ok1) { long b1 = base - C_SZ;     s1 = q0 * k[b1 + lane] + q1 * k[b1 + 32 + lane]; }
        if (ok2) { long b2 = base - 2 * C_SZ; s2 = q0 * k[b2 + lane] + q1 * k[b2 + 32 + lane]; }

        #pragma unroll
        for (int off = 16; off; off >>= 1) {
            s0 += __shfl_xor_sync(0xffffffffu, s0, off);
            s1 += __shfl_xor_sync(0xffffffffu, s1, off);
            s2 += __shfl_xor_sync(0xffffffffu, s2, off);
        }
        s0 *= scale; s1 *= scale; s2 *= scale;

        float m = s0;
        if (ok1 && s1 > m) m = s1;
        if (ok2 && s2 > m) m = s2;
        float p0 = __expf(s0 - m);
        float p1 = ok1 ? __expf(s1 - m) : 0.f;
        float p2 = ok2 ? __expf(s2 - m) : 0.f;
        float inv = 1.f / (p0 + p1 + p2);
        p0 *= inv; p1 *= inv; p2 *= inv;

        float y0 = p0 * vv[base + lane];
        float y1 = p0 * vv[base + 32 + lane];
        if (ok1) { long b1 = base - C_SZ;     y0 += p1 * vv[b1 + lane]; y1 += p1 * vv[b1 + 32 + lane]; }
        if (ok2) { long b2 = base - 2 * C_SZ; y0 += p2 * vv[b2 + lane]; y1 += p2 * vv[b2 + 32 + lane]; }

        y[base + lane]      = f2tf32(y0);
        y[base + 32 + lane] = f2tf32(y1);
    }
}

// ---------------------------------------------------------------------------
extern "C" void kernel_launch(void* const* d_in, const int* in_sizes, int n_in,
                              void* d_out, int out_size)
{
    const float* x  = (const float*)d_in[0];
    const float* Wq = (const float*)d_in[1];
    const float* bq = (const float*)d_in[2];
    const float* Wk = (const float*)d_in[3];
    const float* bk = (const float*)d_in[4];
    const float* Wv = (const float*)d_in[5];
    const float* bv = (const float*)d_in[6];
    const float* Wo = (const float*)d_in[7];
    const float* bo = (const float*)d_in[8];
    float* out = (float*)d_out;

    void *pxc, *pwc, *pq, *pk, *pv, *py;
    cudaGetSymbolAddress(&pxc, g_xc);
    cudaGetSymbolAddress(&pwc, g_wc);
    cudaGetSymbolAddress(&pq, g_q);
    cudaGetSymbolAddress(&pk, g_k);
    cudaGetSymbolAddress(&pv, g_v);
    cudaGetSymbolAddress(&py, g_y);
    float* xc = (float*)pxc;
    float* wc = (float*)pwc;   // 4 contiguous [C*C] blocks

    cudaFuncSetAttribute(gemm_tc, cudaFuncAttributeMaxDynamicSharedMemorySize,
                         SM_TOTAL);

    // tf32(rna) pre-rounding
    const long NX4 = (long)M_TOT * C_SZ / 4;
    const long NW4 = (long)C_SZ * C_SZ / 4;
    conv_tf32<<<2048, 256>>>(x, xc, NX4);
    conv_tf32<<<512, 256>>>(Wq, wc + 0 * (long)C_SZ * C_SZ, NW4);
    conv_tf32<<<512, 256>>>(Wk, wc + 1 * (long)C_SZ * C_SZ, NW4);
    conv_tf32<<<512, 256>>>(Wv, wc + 2 * (long)C_SZ * C_SZ, NW4);
    conv_tf32<<<512, 256>>>(Wo, wc + 3 * (long)C_SZ * C_SZ, NW4);

    dim3 grid(C_SZ / BN, M_TOT / BM);   // (4, 256)
    gemm_tc<<<grid, 512, SM_TOTAL>>>(xc, wc + 0 * (long)C_SZ * C_SZ, bq, (float*)pq);
    gemm_tc<<<grid, 512, SM_TOTAL>>>(xc, wc + 1 * (long)C_SZ * C_SZ, bk, (float*)pk);
    gemm_tc<<<grid, 512, SM_TOTAL>>>(xc, wc + 2 * (long)C_SZ * C_SZ, bv, (float*)pv);

    attn_band3<<<M_TOT / 4, 128>>>((const float*)pq, (const float*)pk,
                                   (const float*)pv, (float*)py);

    gemm_tc<<<grid, 512, SM_TOTAL>>>((const float*)py,
                                     wc + 3 * (long)C_SZ * C_SZ, bo, out);
}

// round 14
// speedup vs baseline: 2.2327x; 1.7595x over previous
#include <cuda_runtime.h>
#include <cuda_fp16.h>
#include <cstdint>

// Problem constants
#define B_SZ   8
#define T_SZ   4096
#define C_SZ   1024
#define M_TOT  (B_SZ * T_SZ)       // 32768
#define H_SZ   16
#define D_SZ   64

// ---------------- scratch (static device globals, no runtime alloc) --------
__device__ __half g_xh[(size_t)M_TOT * C_SZ];         // fp16 x
__device__ __half g_wh[4][(size_t)C_SZ * C_SZ];       // fp16 weights
__device__ float  g_q[(size_t)M_TOT * C_SZ];
__device__ float  g_k[(size_t)M_TOT * C_SZ];
__device__ float  g_v[(size_t)M_TOT * C_SZ];
__device__ __half g_yh[(size_t)M_TOT * C_SZ];         // fp16 attn out

// ---------------- helpers ---------------------------------------------------
__device__ __forceinline__ uint32_t smem_u32(const void* p) {
    uint32_t a;
    asm("{ .reg .u64 t; cvta.to.shared.u64 t, %1; cvt.u32.u64 %0, t; }"
        : "=r"(a) : "l"(p));
    return a;
}
__device__ __forceinline__ void cp16(uint32_t dst, const void* src) {
    asm volatile("cp.async.cg.shared.global [%0], [%1], 16;"
                 :: "r"(dst), "l"(src) : "memory");
}
#define CP_COMMIT() asm volatile("cp.async.commit_group;" ::: "memory")
#define CP_WAIT(n)  asm volatile("cp.async.wait_group %0;" :: "n"(n) : "memory")

__device__ __forceinline__ void ldsm4(uint32_t* r, uint32_t addr) {
    asm volatile("ldmatrix.sync.aligned.m8n8.x4.shared.b16 {%0,%1,%2,%3}, [%4];"
                 : "=r"(r[0]), "=r"(r[1]), "=r"(r[2]), "=r"(r[3]) : "r"(addr));
}
__device__ __forceinline__ void mma16(float* c, const uint32_t* a,
                                      uint32_t b0, uint32_t b1) {
    asm volatile(
        "mma.sync.aligned.m16n8k16.row.col.f32.f16.f16.f32 "
        "{%0,%1,%2,%3},{%4,%5,%6,%7},{%8,%9},{%0,%1,%2,%3};\n"
        : "+f"(c[0]), "+f"(c[1]), "+f"(c[2]), "+f"(c[3])
        : "r"(a[0]), "r"(a[1]), "r"(a[2]), "r"(a[3]), "r"(b0), "r"(b1));
}

// ---------------- GEMM: C[M,1024] = A[M,1024] @ W[1024,1024]^T + bias ------
// mma.sync fp16 m16n8k16, fp32 accum. BM=128 BN=256, K-chunk=64 halves,
// 512 threads (16 warps 4x4), 3-stage cp.async, ldmatrix.x4.
#define BM 128
#define BN 256
#define BKH 64                        // halves per chunk (128 B rows)
#define SAH 72                        // padded halves per smem row (144 B)
#define A_STH (BM * SAH)              // 9216 halves
#define B_STH (BN * SAH)              // 18432 halves
#define STG_H (A_STH + B_STH)         // 27648 halves = 55296 B
#define STAGES 3
#define NCH (C_SZ / BKH)              // 16
#define SM_TOTAL (STAGES * STG_H * 2) // 165888 B

__global__ __launch_bounds__(512, 1)
void gemm_fp16(const __half* __restrict__ A, const __half* __restrict__ W,
               const float* __restrict__ bias, float* __restrict__ C)
{
    extern __shared__ __align__(128) __half smem[];
    const uint32_t sbase = smem_u32(smem);

    const int tid  = threadIdx.x;
    const int lane = tid & 31;
    const int wid  = tid >> 5;
    const int wm   = wid & 3;     // 0..3 -> 32 rows
    const int wn   = wid >> 2;    // 0..3 -> 64 cols
    const int g    = lane >> 2;
    const int tc   = lane & 3;

    const long bM = (long)blockIdx.y * BM;
    const long bN = (long)blockIdx.x * BN;
    const __half* Ab = A + bM * C_SZ;
    const __half* Wb = W + bN * C_SZ;

    // loader: A 128 rows x 128B = 1024 x 16B (2/thread); B 256 x 128B (4/thread)
    auto load_chunk = [&](int t, int s) {
        const int k0 = t * BKH;                       // in halves
        const uint32_t as = sbase + (uint32_t)(s * STG_H) * 2;
        const uint32_t bs = as + A_STH * 2;
        #pragma unroll
        for (int i = 0; i < 2; i++) {
            int idx = tid + i * 512;
            int row = idx >> 3, c = idx & 7;          // c16 in 16B units
            cp16(as + (uint32_t)(row * SAH * 2 + c * 16),
                 Ab + (long)row * C_SZ + k0 + c * 8);
        }
        #pragma unroll
        for (int i = 0; i < 4; i++) {
            int idx = tid + i * 512;
            int row = idx >> 3, c = idx & 7;
            cp16(bs + (uint32_t)(row * SAH * 2 + c * 16),
                 Wb + (long)row * C_SZ + k0 + c * 8);
        }
    };

    // ldmatrix base offsets (bytes within a stage)
    // A (per 16-row tile): lanes 0-7 rows+0 @k0 | 8-15 rows+8 @k0
    //                      | 16-23 rows+0 @k8 | 24-31 rows+8 @k8
    const uint32_t aoff =
        (uint32_t)((wm * 32 + ((lane >> 3) & 1) * 8 + (lane & 7)) * SAH * 2
                   + (lane >> 4) * 16);
    // B (per n16 pair p): lanes 0-7 n+0 @k0 | 8-15 n+0 @k8
    //                     | 16-23 n+8 @k0 | 24-31 n+8 @k8
    const uint32_t boff = (uint32_t)A_STH * 2 +
        (uint32_t)((wn * 64 + (lane >> 4) * 8 + (lane & 7)) * SAH * 2
                   + ((lane >> 3) & 1) * 16);

    float acc[2][8][4] = {};

    load_chunk(0, 0); CP_COMMIT();
    load_chunk(1, 1); CP_COMMIT();

    for (int t = 0; t < NCH; t++) {
        if (t + 2 < NCH) load_chunk(t + 2, (t + 2) % STAGES);
        CP_COMMIT();
        CP_WAIT(2);
        __syncthreads();

        const uint32_t stg = sbase + (uint32_t)((t % STAGES) * STG_H) * 2;
        #pragma unroll
        for (int kk = 0; kk < BKH / 16; kk++) {       // 4 iters of k16
            const uint32_t kb = kk * 32;              // 16 halves = 32 bytes
            uint32_t a[2][4];
            ldsm4(a[0], stg + aoff + kb);
            ldsm4(a[1], stg + aoff + (uint32_t)(16 * SAH * 2) + kb);
            #pragma unroll
            for (int p = 0; p < 4; p++) {
                uint32_t b[4];
                ldsm4(b, stg + boff + (uint32_t)(p * 16 * SAH * 2) + kb);
                // b0,b1 -> n-tile 2p ; b2,b3 -> n-tile 2p+1
                mma16(acc[0][2 * p],     a[0], b[0], b[1]);
                mma16(acc[1][2 * p],     a[1], b[0], b[1]);
                mma16(acc[0][2 * p + 1], a[0], b[2], b[3]);
                mma16(acc[1][2 * p + 1], a[1], b[2], b[3]);
            }
        }
        __syncthreads();
    }

    // epilogue: bias add + store (fp32)
    #pragma unroll
    for (int mi = 0; mi < 2; mi++) {
        long r0 = bM + wm * 32 + mi * 16 + g;
        #pragma unroll
        for (int ni = 0; ni < 8; ni++) {
            long c = bN + wn * 64 + ni * 8 + tc * 2;
            float bb0 = bias[c], bb1 = bias[c + 1];
            float2 o0 = make_float2(acc[mi][ni][0] + bb0, acc[mi][ni][1] + bb1);
            float2 o1 = make_float2(acc[mi][ni][2] + bb0, acc[mi][ni][3] + bb1);
            *(float2*)(C + r0 * C_SZ + c)       = o0;
            *(float2*)(C + (r0 + 8) * C_SZ + c) = o1;
        }
    }
}

// ---------------- fp32 -> fp16 elementwise ---------------------------------
__global__ void conv_f2h(const float* __restrict__ in, __half* __restrict__ out,
                         long n4)
{
    long i = (long)blockIdx.x * blockDim.x + threadIdx.x;
    long stride = (long)gridDim.x * blockDim.x;
    for (; i < n4; i += stride) {
        float4 v = ((const float4*)in)[i];
        __half2 h0 = __floats2half2_rn(v.x, v.y);
        __half2 h1 = __floats2half2_rn(v.z, v.w);
        uint32_t u0 = *(uint32_t*)&h0, u1 = *(uint32_t*)&h1;
        ((uint2*)out)[i] = make_uint2(u0, u1);
    }
}

// ---------------- banded window-3 attention (y -> fp16) --------------------
__global__ __launch_bounds__(128)
void attn_band3(const float* __restrict__ q, const float* __restrict__ k,
                const float* __restrict__ vv, __half* __restrict__ y)
{
    const int lane = threadIdx.x & 31;
    const int warp = threadIdx.x >> 5;
    const long r = (long)blockIdx.x * 4 + warp;
    const int  t = (int)(r & (T_SZ - 1));
    const bool ok1 = (t >= 1), ok2 = (t >= 2);
    const float scale = 0.125f;
    const long rowb = r * C_SZ;

    #pragma unroll 2
    for (int h = 0; h < H_SZ; h++) {
        const long base = rowb + h * D_SZ;
        float q0 = q[base + lane], q1 = q[base + 32 + lane];

        float s0 = q0 * k[base + lane] + q1 * k[base + 32 + lane];
        float s1 = 0.f, s2 = 0.f;
        if (ok1) { long b1 = base - C_SZ;     s1 = q0 * k[b1 + lane] + q1 * k[b1 + 32 + lane]; }
        if (ok2) { long b2 = base - 2 * C_SZ; s2 = q0 * k[b2 + lane] + q1 * k[b2 + 32 + lane]; }

        #pragma unroll
        for (int off = 16; off; off >>= 1) {
            s0 += __shfl_xor_sync(0xffffffffu, s0, off);
            s1 += __shfl_xor_sync(0xffffffffu, s1, off);
            s2 += __shfl_xor_sync(0xffffffffu, s2, off);
        }
        s0 *= scale; s1 *= scale; s2 *= scale;

        float m = s0;
        if (ok1 && s1 > m) m = s1;
        if (ok2 && s2 > m) m = s2;
        float p0 = __expf(s0 - m);
        float p1 = ok1 ? __expf(s1 - m) : 0.f;
        float p2 = ok2 ? __expf(s2 - m) : 0.f;
        float inv = 1.f / (p0 + p1 + p2);
        p0 *= inv; p1 *= inv; p2 *= inv;

        float y0 = p0 * vv[base + lane];
        float y1 = p0 * vv[base + 32 + lane];
        if (ok1) { long b1 = base - C_SZ;     y0 += p1 * vv[b1 + lane]; y1 += p1 * vv[b1 + 32 + lane]; }
        if (ok2) { long b2 = base - 2 * C_SZ; y0 += p2 * vv[b2 + lane]; y1 += p2 * vv[b2 + 32 + lane]; }

        y[base + lane]      = __float2half_rn(y0);
        y[base + 32 + lane] = __float2half_rn(y1);
    }
}

// ---------------------------------------------------------------------------
extern "C" void kernel_launch(void* const* d_in, const int* in_sizes, int n_in,
                              void* d_out, int out_size)
{
    const float* x  = (const float*)d_in[0];
    const float* Wq = (const float*)d_in[1];
    const float* bq = (const float*)d_in[2];
    const float* Wk = (const float*)d_in[3];
    const float* bk = (const float*)d_in[4];
    const float* Wv = (const float*)d_in[5];
    const float* bv = (const float*)d_in[6];
    const float* Wo = (const float*)d_in[7];
    const float* bo = (const float*)d_in[8];
    float* out = (float*)d_out;

    void *pxh, *pwh, *pq, *pk, *pv, *pyh;
    cudaGetSymbolAddress(&pxh, g_xh);
    cudaGetSymbolAddress(&pwh, g_wh);
    cudaGetSymbolAddress(&pq, g_q);
    cudaGetSymbolAddress(&pk, g_k);
    cudaGetSymbolAddress(&pv, g_v);
    cudaGetSymbolAddress(&pyh, g_yh);
    __half* xh = (__half*)pxh;
    __half* wh = (__half*)pwh;   // 4 contiguous [C*C] blocks

    cudaFuncSetAttribute(gemm_fp16, cudaFuncAttributeMaxDynamicSharedMemorySize,
                         SM_TOTAL);

    // fp32 -> fp16 conversion
    const long NX4 = (long)M_TOT * C_SZ / 4;
    const long NW4 = (long)C_SZ * C_SZ / 4;
    conv_f2h<<<2048, 256>>>(x, xh, NX4);
    conv_f2h<<<512, 256>>>(Wq, wh + 0 * (long)C_SZ * C_SZ, NW4);
    conv_f2h<<<512, 256>>>(Wk, wh + 1 * (long)C_SZ * C_SZ, NW4);
    conv_f2h<<<512, 256>>>(Wv, wh + 2 * (long)C_SZ * C_SZ, NW4);
    conv_f2h<<<512, 256>>>(Wo, wh + 3 * (long)C_SZ * C_SZ, NW4);

    dim3 grid(C_SZ / BN, M_TOT / BM);   // (4, 256)
    gemm_fp16<<<grid, 512, SM_TOTAL>>>(xh, wh + 0 * (long)C_SZ * C_SZ, bq, (float*)pq);
    gemm_fp16<<<grid, 512, SM_TOTAL>>>(xh, wh + 1 * (long)C_SZ * C_SZ, bk, (float*)pk);
    gemm_fp16<<<grid, 512, SM_TOTAL>>>(xh, wh + 2 * (long)C_SZ * C_SZ, bv, (float*)pv);

    attn_band3<<<M_TOT / 4, 128>>>((const float*)pq, (const float*)pk,
                                   (const float*)pv, (__half*)pyh);

    gemm_fp16<<<grid, 512, SM_TOTAL>>>((const __half*)pyh,
                                       wh + 3 * (long)C_SZ * C_SZ, bo, out);
}